// round 2
// baseline (speedup 1.0000x reference)
#include <cuda_runtime.h>

#define BATCH       16384
#define NUM_FIELDS  20
#define NUM_FEAT    100000
#define LATENT      64

// One warp per batch row, two fields per load instruction:
//   lanes 0-15  gather field 2f   (float4 each -> 256B coalesced)
//   lanes 16-31 gather field 2f+1 (float4 each -> 256B coalesced)
// 10 independent LDG.128 per warp (vs 20 LDG.64 before): half the LSU issue
// work, double the in-flight bytes per instruction.
__global__ void __launch_bounds__(256, 6)
ffm_kernel(const int* __restrict__ x,
           const float* __restrict__ emb,
           float* __restrict__ out)
{
    const int warp = (blockIdx.x * blockDim.x + threadIdx.x) >> 5;
    const int lane = threadIdx.x & 31;
    if (warp >= BATCH) return;

    const int half = lane >> 4;    // 0: even fields, 1: odd fields
    const int l16  = lane & 15;    // owns latent dims [4*l16, 4*l16+3]

    // Lanes 0..19 hold this row's feature indices (also the linear term).
    int xv = 0;
    if (lane < NUM_FIELDS) xv = __ldg(&x[warp * NUM_FIELDS + lane]);

    float4 s   = make_float4(0.f, 0.f, 0.f, 0.f);
    float  ssq = 0.f;

    #pragma unroll
    for (int fp = 0; fp < NUM_FIELDS / 2; fp++) {
        const int field = 2 * fp + half;
        const int idx   = __shfl_sync(0xffffffffu, xv, field);
        const float4 v  = __ldg(reinterpret_cast<const float4*>(
            emb + ((size_t)field * NUM_FEAT + (size_t)idx) * LATENT) + l16);
        s.x += v.x;  s.y += v.y;  s.z += v.z;  s.w += v.w;
        ssq  = fmaf(v.x, v.x, fmaf(v.y, v.y, fmaf(v.z, v.z, fmaf(v.w, v.w, ssq))));
    }

    // Combine the two field-halves: lanes l and l+16 own the same 4 dims.
    s.x += __shfl_xor_sync(0xffffffffu, s.x, 16);
    s.y += __shfl_xor_sync(0xffffffffu, s.y, 16);
    s.z += __shfl_xor_sync(0xffffffffu, s.z, 16);
    s.w += __shfl_xor_sync(0xffffffffu, s.w, 16);
    ssq += __shfl_xor_sync(0xffffffffu, ssq, 16);

    // Per-lane partial of (sum_d s_d^2 - sum v^2); identical in lane pairs
    // (l, l+16) after the xor-combine, so reduce over lanes 0..15 only.
    float t = fmaf(s.x, s.x, fmaf(s.y, s.y, fmaf(s.z, s.z, s.w * s.w))) - ssq;
    #pragma unroll
    for (int off = 8; off > 0; off >>= 1)
        t += __shfl_down_sync(0xffffffffu, t, off);

    // Linear term: sum of xv over all lanes (lanes >= 20 contribute 0).
    float lin = (float)xv;
    #pragma unroll
    for (int off = 16; off > 0; off >>= 1)
        lin += __shfl_down_sync(0xffffffffu, lin, off);

    if (lane == 0) out[warp] = lin + 0.5f * t;
}

extern "C" void kernel_launch(void* const* d_in, const int* in_sizes, int n_in,
                              void* d_out, int out_size)
{
    const int*   x   = (const int*)d_in[0];
    // d_in[1] = field_indices (0..19), implicit in layout.
    const float* emb = (const float*)d_in[2];
    float*       out = (float*)d_out;

    const int warps_per_block = 256 / 32;                              // 8
    const int blocks = (BATCH + warps_per_block - 1) / warps_per_block; // 2048
    ffm_kernel<<<blocks, 256>>>(x, emb, out);
}